// round 15
// baseline (speedup 1.0000x reference)
#include <cuda_runtime.h>
#include <cuda_fp16.h>
#include <stdint.h>

// Problem constants: N=200000 nodes, D=64, E=4000000 edges, 3 layers.
#define MAX_N 200000
#define DIM   64
#define MAX_E 4000000
#define PBLK  256
#define PGRID 1184              // 148 SMs x 8 blocks; __launch_bounds__ guarantees residency
#define MAX_NBLK 1024           // partial-sum slots (N/256 = 782 used)
// CSR capacity with per-bucket padding to multiple of 4:
#define MAX_CSR (MAX_E + 3 * MAX_N + 4)

// Scratch (__device__ globals — allocation-free rule). Only referenced from
// device code (host shadow addresses are silently wrong on ATS).
__device__ __align__(128) int    g_deg[MAX_N];      // in-degree histogram
__device__ __align__(128) float  g_dinv[MAX_N];     // deg^{-1/2}
__device__ __align__(128) float  g_dinv2[MAX_N];    // deg^{-1}
__device__ __align__(128) float  g_rdeg[MAX_N];     // sqrt(deg) (0 if deg==0)
__device__ __align__(128) int    g_rowptr[MAX_N];   // padded CSR bucket starts (16B-aligned)
__device__ __align__(128) int    g_partial[MAX_NBLK];
__device__ __align__(128) int    g_csrc[MAX_CSR];   // CSR: source node per slot (pad -> N)
__device__ __align__(128) int2   g_edge[MAX_E];     // decoded (src, dst) per edge
__device__ __align__(128) int    g_rank[MAX_E];     // per-edge rank within dst bucket
// Grid-barrier state (generation-based; self-resetting => replay-deterministic).
__device__ unsigned g_bar_count;
__device__ unsigned g_bar_gen;
// Propagated state y_k = dinv .* e_k, fp16 (fp32 accumulation).
// Row N is a sentinel ZERO row targeted by CSR padding slots.
__device__ __align__(128) __half g_y0[(size_t)(MAX_N + 1) * DIM];
__device__ __align__(128) __half g_y1[(size_t)(MAX_N + 1) * DIM];
__device__ __align__(128) __half g_y2[(size_t)(MAX_N + 1) * DIM];

// ---- dtype mini-probe: int64 little-endian with values < 2^31 -> every odd
// int32 word is 0; impossible for 32 consecutive int32 node ids. ----
__device__ __forceinline__ int probe_is64(const int* __restrict__ ei32) {
    int all_zero = 1;
    for (int i = 0; i < 32; i++)
        if (__ldg(&ei32[2 * i + 1]) != 0) { all_zero = 0; break; }
    return all_zero;
}

// ---- software grid barrier (all PGRID blocks resident by construction) ----
__device__ __forceinline__ void grid_barrier() {
    __syncthreads();
    if (threadIdx.x == 0) {
        __threadfence();                                   // release phase data
        unsigned gen = atomicAdd(&g_bar_gen, 0u);          // read current generation
        if (atomicAdd(&g_bar_count, 1u) == PGRID - 1) {
            atomicExch(&g_bar_count, 0u);                  // reset before release
            __threadfence();
            atomicAdd(&g_bar_gen, 1u);                     // release waiters
        } else {
            while (atomicAdd(&g_bar_gen, 0u) == gen) { }   // spin
        }
        __threadfence();                                   // acquire phase data
    }
    __syncthreads();
}

// ================= persistent fused prologue =================
// A: zero deg | B: decode+histogram+rank | C1..C3: padded-degree scan ->
// rowptr + sentinels + dinv tables | E: y0 cast | D: CSR fill (E,D independent)
__global__ __launch_bounds__(PBLK, 8)
void prologue_kernel(const int* __restrict__ ei32, const float* __restrict__ emb0,
                     int E, int N) {
    __shared__ int sh[PBLK];
    __shared__ int sh_run;
    __shared__ int sh_is64;
    int tid  = threadIdx.x;
    int bid  = blockIdx.x;
    int gsz  = gridDim.x * PBLK;
    int gtid = bid * PBLK + tid;

    if (tid == 0) sh_is64 = probe_is64(ei32);
    __syncthreads();
    int is64 = sh_is64;

    // --- A: zero degree histogram ---
    for (int i = gtid; i < N; i += gsz) g_deg[i] = 0;
    grid_barrier();

    // --- B: edge decode + histogram; atomic's return IS the rank ---
    for (int e = gtid; e < E; e += gsz) {
        int s, d;
        if (is64) {
            int2 ws = __ldg(reinterpret_cast<const int2*>(ei32) + e);
            int2 wd = __ldg(reinterpret_cast<const int2*>(ei32) + (size_t)E + e);
            s = ws.x; d = wd.x;
        } else {
            s = __ldg(&ei32[e]);
            d = __ldg(&ei32[(size_t)E + e]);
        }
        s = min(max(s, 0), N - 1);       // surprise -> wrong answer, not trap
        d = min(max(d, 0), N - 1);
        g_edge[e] = make_int2(s, d);
        g_rank[e] = atomicAdd(&g_deg[d], 1);
    }
    grid_barrier();

    int nblk = (N + PBLK - 1) / PBLK;

    // --- C1: per-chunk sums of padded degrees ---
    for (int c = bid; c < nblk; c += gridDim.x) {
        int i = c * PBLK + tid;
        int deg = (i < N) ? g_deg[i] : 0;
        sh[tid] = (deg + 3) & ~3;
        __syncthreads();
        for (int s = PBLK / 2; s > 0; s >>= 1) {
            if (tid < s) sh[tid] += sh[tid + s];
            __syncthreads();
        }
        if (tid == 0) g_partial[c] = sh[0];
        __syncthreads();
    }
    grid_barrier();

    // --- C2: block 0 exclusive-scans the chunk sums ---
    if (bid == 0) {
        if (tid == 0) sh_run = 0;
        __syncthreads();
        for (int base = 0; base < nblk; base += PBLK) {
            int idx = base + tid;
            int v = (idx < nblk) ? g_partial[idx] : 0;
            sh[tid] = v;
            __syncthreads();
            for (int off = 1; off < PBLK; off <<= 1) {
                int t = (tid >= off) ? sh[tid - off] : 0;
                __syncthreads();
                sh[tid] += t;
                __syncthreads();
            }
            if (idx < nblk) g_partial[idx] = sh[tid] - v + sh_run;
            __syncthreads();
            if (tid == 0) sh_run += sh[PBLK - 1];
            __syncthreads();
        }
    }
    grid_barrier();

    // --- C3: rowptr + sentinel padding + dinv tables ---
    for (int c = bid; c < nblk; c += gridDim.x) {
        int i = c * PBLK + tid;
        int deg = (i < N) ? g_deg[i] : 0;
        int v = (deg + 3) & ~3;
        sh[tid] = v;
        __syncthreads();
        for (int off = 1; off < PBLK; off <<= 1) {
            int t = (tid >= off) ? sh[tid - off] : 0;
            __syncthreads();
            sh[tid] += t;
            __syncthreads();
        }
        if (i < N) {
            int excl = sh[tid] - v + g_partial[c];
            g_rowptr[i] = excl;
            for (int j = excl + deg; j < excl + v; j++)   // <=3 sentinel slots
                g_csrc[j] = N;
            float di = (deg > 0) ? rsqrtf((float)deg) : 0.f;  // deg>=1 => max(deg,1)==deg
            g_dinv[i]  = di;
            g_dinv2[i] = di * di;
            g_rdeg[i]  = (deg > 0) ? sqrtf((float)deg) : 0.f;
        }
        __syncthreads();
    }
    grid_barrier();

    // --- E: y0 = dinv .* emb0 (fp16) + sentinel row zeroing ---
    int tot = N * 32;
    for (int t2 = gtid; t2 < tot + 32; t2 += gsz) {
        if (t2 >= tot) {                                   // sentinel row chunks
            half2 z = __floats2half2_rn(0.f, 0.f);
            reinterpret_cast<half2*>(g_y0)[t2] = z;
            reinterpret_cast<half2*>(g_y1)[t2] = z;
            reinterpret_cast<half2*>(g_y2)[t2] = z;
        } else {
            int node = t2 >> 5;
            float di = __ldg(&g_dinv[node]);
            float2 v = __ldg(reinterpret_cast<const float2*>(emb0) + t2);
            reinterpret_cast<half2*>(g_y0)[t2] = __floats2half2_rn(di * v.x, di * v.y);
        }
    }

    // --- D: CSR fill (independent of E; completes by kernel end) ---
    for (int e = gtid; e < E; e += gsz) {
        int2 sd = __ldg(&g_edge[e]);
        int pos = __ldg(&g_rowptr[sd.y]) + __ldg(&g_rank[e]);
        g_csrc[pos] = sd.x;
    }
}

// ---------------- propagation layer: y_out[d] = dinv2[d] * sum y_in[src]
// One warp per node; lane owns one half2 (4B) of the 128B fp16 row. Indices
// read 4-at-a-time via uniform int4 LDG, software-pipelined. Padding slots
// hit the sentinel zero row.
__global__ void layer_kernel(int layer, int N) {
    int warp = (blockIdx.x * blockDim.x + threadIdx.x) >> 5;
    int lane = threadIdx.x & 31;
    if (warp >= N) return;

    const half2* inp  = reinterpret_cast<const half2*>((layer == 0) ? g_y0 : g_y1);
    half2*       outp = reinterpret_cast<half2*>((layer == 0) ? g_y1 : g_y2);

    int beg = __ldg(&g_rowptr[warp]);
    int cnt = __ldg(&g_deg[warp]);
    int nq  = (cnt + 3) >> 2;
    const int4* qp = reinterpret_cast<const int4*>(g_csrc + beg);

    float2 acc = make_float2(0.f, 0.f);
    if (nq > 0) {
        int4 q = __ldg(qp);
        #pragma unroll 2
        for (int b = 1; b < nq; b++) {
            int4 qn = __ldg(qp + b);               // prefetch next indices
            float2 v0 = __half22float2(__ldg(&inp[(size_t)q.x * 32 + lane]));
            float2 v1 = __half22float2(__ldg(&inp[(size_t)q.y * 32 + lane]));
            float2 v2 = __half22float2(__ldg(&inp[(size_t)q.z * 32 + lane]));
            float2 v3 = __half22float2(__ldg(&inp[(size_t)q.w * 32 + lane]));
            acc.x += v0.x + v1.x + v2.x + v3.x;
            acc.y += v0.y + v1.y + v2.y + v3.y;
            q = qn;
        }
        float2 v0 = __half22float2(__ldg(&inp[(size_t)q.x * 32 + lane]));
        float2 v1 = __half22float2(__ldg(&inp[(size_t)q.y * 32 + lane]));
        float2 v2 = __half22float2(__ldg(&inp[(size_t)q.z * 32 + lane]));
        float2 v3 = __half22float2(__ldg(&inp[(size_t)q.w * 32 + lane]));
        acc.x += v0.x + v1.x + v2.x + v3.x;
        acc.y += v0.y + v1.y + v2.y + v3.y;
    }
    float w = __ldg(&g_dinv2[warp]);
    outp[(size_t)warp * 32 + lane] = __floats2half2_rn(w * acc.x, w * acc.y);
}

// ------- fused last layer + finalize:
// y3[d] = dinv2[d] * sum y2[src]   (never stored)
// out[0:nd)  = emb0
// out[nd:2nd)= (e0 + sqrt(deg[d])*(y1+y2+y3)) / 4
__global__ void layer3_finalize_kernel(const float* __restrict__ emb0,
                                       float* __restrict__ out, int N, long long nd2) {
    int warp = (blockIdx.x * blockDim.x + threadIdx.x) >> 5;
    int lane = threadIdx.x & 31;
    if (warp >= N) return;

    int beg = __ldg(&g_rowptr[warp]);
    int cnt = __ldg(&g_deg[warp]);
    int nq  = (cnt + 3) >> 2;
    const int4* qp = reinterpret_cast<const int4*>(g_csrc + beg);
    const half2* y2p = reinterpret_cast<const half2*>(g_y2);

    float2 acc = make_float2(0.f, 0.f);
    if (nq > 0) {
        int4 q = __ldg(qp);
        #pragma unroll 2
        for (int b = 1; b < nq; b++) {
            int4 qn = __ldg(qp + b);               // prefetch next indices
            float2 v0 = __half22float2(__ldg(&y2p[(size_t)q.x * 32 + lane]));
            float2 v1 = __half22float2(__ldg(&y2p[(size_t)q.y * 32 + lane]));
            float2 v2 = __half22float2(__ldg(&y2p[(size_t)q.z * 32 + lane]));
            float2 v3 = __half22float2(__ldg(&y2p[(size_t)q.w * 32 + lane]));
            acc.x += v0.x + v1.x + v2.x + v3.x;
            acc.y += v0.y + v1.y + v2.y + v3.y;
            q = qn;
        }
        float2 v0 = __half22float2(__ldg(&y2p[(size_t)q.x * 32 + lane]));
        float2 v1 = __half22float2(__ldg(&y2p[(size_t)q.y * 32 + lane]));
        float2 v2 = __half22float2(__ldg(&y2p[(size_t)q.z * 32 + lane]));
        float2 v3 = __half22float2(__ldg(&y2p[(size_t)q.w * 32 + lane]));
        acc.x += v0.x + v1.x + v2.x + v3.x;
        acc.y += v0.y + v1.y + v2.y + v3.y;
    }
    float w2 = __ldg(&g_dinv2[warp]);
    float rd = __ldg(&g_rdeg[warp]);
    long long idxo = (long long)warp * 32 + lane;

    float2 e0 = __ldg(reinterpret_cast<const float2*>(emb0) + idxo);
    float2 h1 = __half22float2(__ldg(reinterpret_cast<const half2*>(g_y1) + idxo));
    float2 h2 = __half22float2(__ldg(y2p + idxo));

    float2 r;
    r.x = 0.25f * (e0.x + rd * (h1.x + h2.x + w2 * acc.x));
    r.y = 0.25f * (e0.y + rd * (h1.y + h2.y + w2 * acc.y));

    float2* o = reinterpret_cast<float2*>(out);
    o[idxo] = e0;           // exact fp32 copy of emb0
    o[nd2 + idxo] = r;      // mean embedding
}

extern "C" void kernel_launch(void* const* d_in, const int* in_sizes, int n_in,
                              void* d_out, int out_size) {
    const int*   ei32 = (const int*)d_in[0];     // edge_index [2, E] (int32 or int64)
    const float* emb  = (const float*)d_in[1];   // emb_weight [N, D] float32
    int       E   = in_sizes[0] / 2;
    long long nd  = (long long)in_sizes[1];
    int       N   = (int)(nd / DIM);
    long long nd2 = nd / 2;                      // number of float2 chunks
    float* out = (float*)d_out;

    int wblk = (N * 32 + 255) / 256;             // one warp per node

    prologue_kernel<<<PGRID, PBLK>>>(ei32, emb, E, N);
    layer_kernel<<<wblk, 256>>>(0, N);
    layer_kernel<<<wblk, 256>>>(1, N);
    layer3_finalize_kernel<<<wblk, 256>>>(emb, out, N, nd2);
}

// round 16
// speedup vs baseline: 1.0851x; 1.0851x over previous
#include <cuda_runtime.h>
#include <cuda_fp16.h>
#include <stdint.h>

// Problem constants: N=200000 nodes, D=64, E=4000000 edges, 3 layers.
#define MAX_N 200000
#define DIM   64
#define MAX_E 4000000
#define SCAN_BLK 256
#define MAX_NBLK 1024   // supports N up to 256*1024
// CSR capacity with per-bucket padding to multiple of 4:
#define MAX_CSR (MAX_E + 3 * MAX_N + 4)

// Scratch (__device__ globals — allocation-free rule). Only referenced from
// device code (host shadow addresses are silently wrong on ATS).
__device__ __align__(128) int    g_deg[MAX_N];      // in-degree histogram
__device__ __align__(128) float  g_dinv[MAX_N];     // deg^{-1/2}
__device__ __align__(128) float  g_dinv2[MAX_N];    // deg^{-1}
__device__ __align__(128) float  g_rdeg[MAX_N];     // sqrt(deg) (0 if deg==0)
__device__ __align__(128) int    g_rowptr[MAX_N];   // padded CSR bucket starts (16B-aligned)
__device__ __align__(128) int    g_cursor[MAX_N];   // atomic fill cursors
__device__ __align__(128) int    g_partial[MAX_NBLK];
__device__ __align__(128) int    g_csrc[MAX_CSR];   // CSR: PRESCALED src row offsets (src*32; pad -> N*32)
__device__ __align__(128) int2   g_edge[MAX_E];     // decoded (src, dst) per edge
// Propagated state y_k = dinv .* e_k, fp16 (fp32 accumulation).
// Row N is a sentinel ZERO row targeted by CSR padding slots.
__device__ __align__(128) __half g_y0[(size_t)(MAX_N + 1) * DIM];
__device__ __align__(128) __half g_y1[(size_t)(MAX_N + 1) * DIM];
__device__ __align__(128) __half g_y2[(size_t)(MAX_N + 1) * DIM];

__global__ void zero_deg_kernel(int N) {
    int i = blockIdx.x * blockDim.x + threadIdx.x;
    if (i < N) g_deg[i] = 0;
}

// ---- dtype mini-probe (per block, reads stay L2/L1-hot) ----
// int64 little-endian with values < 2^31 -> every odd int32 word is 0.
__device__ __forceinline__ int probe_is64(const int* __restrict__ ei32) {
    int all_zero = 1;
    for (int i = 0; i < 32; i++)
        if (__ldg(&ei32[2 * i + 1]) != 0) { all_zero = 0; break; }
    return all_zero;
}

// ---- edge decode + degree histogram (stages decoded pairs in g_edge) ----
__global__ void build_edges_kernel(const int* __restrict__ ei32, int E, int N) {
    __shared__ int sh_is64;
    if (threadIdx.x == 0) sh_is64 = probe_is64(ei32);
    __syncthreads();
    int is64 = sh_is64;

    int e = blockIdx.x * blockDim.x + threadIdx.x;
    if (e >= E) return;
    int s, d;
    if (is64) {
        int2 ws = __ldg(reinterpret_cast<const int2*>(ei32) + e);              // LDG.64
        int2 wd = __ldg(reinterpret_cast<const int2*>(ei32) + (size_t)E + e);  // LDG.64
        s = ws.x; d = wd.x;
    } else {
        s = __ldg(&ei32[e]);
        d = __ldg(&ei32[(size_t)E + e]);
    }
    s = min(max(s, 0), N - 1);           // surprise -> wrong answer, not trap
    d = min(max(d, 0), N - 1);
    g_edge[e] = make_int2(s, d);
    atomicAdd(&g_deg[d], 1);
}

// ---- fused dinv/dinv2/rdeg tables + y0 = dinv .* emb0 (fp16 cast) ----
// Runs on a FORKED stream, concurrent with the scan+fill chain.
// Also zeroes the sentinel row N of y0/y1/y2.
__global__ void dinv_y0_kernel(const float* __restrict__ emb0, int N) {
    int t = blockIdx.x * blockDim.x + threadIdx.x;
    if (t >= N * 32) {
        if (t < N * 32 + 32) {                     // sentinel row chunks
            half2 z = __floats2half2_rn(0.f, 0.f);
            reinterpret_cast<half2*>(g_y0)[t] = z;
            reinterpret_cast<half2*>(g_y1)[t] = z;
            reinterpret_cast<half2*>(g_y2)[t] = z;
        }
        return;
    }
    int node = t >> 5;
    int lane = t & 31;
    int dg = __ldg(&g_deg[node]);                  // warp-broadcast
    float di = (dg > 0) ? rsqrtf((float)dg) : 0.f; // deg>=1 => max(deg,1)==deg
    if (lane == 0) {
        g_dinv[node]  = di;
        g_dinv2[node] = di * di;
        g_rdeg[node]  = (dg > 0) ? sqrtf((float)dg) : 0.f;
    }
    float2 v = __ldg(reinterpret_cast<const float2*>(emb0) + t);
    reinterpret_cast<half2*>(g_y0)[t] = __floats2half2_rn(di * v.x, di * v.y);
}

// ----------------- scans over PADDED degrees ((deg+3)&~3) ------------------
__global__ void scan1_kernel(int N) {
    __shared__ int sh[SCAN_BLK];
    int tid = threadIdx.x;
    int i = blockIdx.x * SCAN_BLK + tid;
    sh[tid] = (i < N) ? ((g_deg[i] + 3) & ~3) : 0;
    __syncthreads();
    for (int s = SCAN_BLK / 2; s > 0; s >>= 1) {
        if (tid < s) sh[tid] += sh[tid + s];
        __syncthreads();
    }
    if (tid == 0) g_partial[blockIdx.x] = sh[0];
}

__global__ void scan2_kernel(int nblk) {
    __shared__ int sh[MAX_NBLK];
    int tid = threadIdx.x;
    int v = (tid < nblk) ? g_partial[tid] : 0;
    sh[tid] = v;
    __syncthreads();
    for (int off = 1; off < MAX_NBLK; off <<= 1) {
        int t = (tid >= off) ? sh[tid - off] : 0;
        __syncthreads();
        sh[tid] += t;
        __syncthreads();
    }
    if (tid < nblk) g_partial[tid] = sh[tid] - v;
}

// per-block exclusive scan + offset -> rowptr; also writes sentinel padding
// (prescaled: N*32 points at the zero row).
__global__ void scan3_kernel(int N) {
    __shared__ int sh[SCAN_BLK];
    int tid = threadIdx.x;
    int i = blockIdx.x * SCAN_BLK + tid;
    int deg = (i < N) ? g_deg[i] : 0;
    int v = (deg + 3) & ~3;
    sh[tid] = v;
    __syncthreads();
    for (int off = 1; off < SCAN_BLK; off <<= 1) {
        int t = (tid >= off) ? sh[tid - off] : 0;
        __syncthreads();
        sh[tid] += t;
        __syncthreads();
    }
    if (i < N) {
        int excl = sh[tid] - v + g_partial[blockIdx.x];
        g_rowptr[i] = excl;
        g_cursor[i] = excl;
        int sent = N * 32;                            // prescaled sentinel
        for (int j = excl + deg; j < excl + v; j++)   // <=3 sentinel slots
            g_csrc[j] = sent;
    }
}

// ------------- CSR fill from staged g_edge (stores PRESCALED src*32) -------
__global__ void fill_kernel(int E) {
    int e = blockIdx.x * blockDim.x + threadIdx.x;
    if (e >= E) return;
    int2 sd = __ldg(&g_edge[e]);
    int pos = atomicAdd(&g_cursor[sd.y], 1);
    g_csrc[pos] = sd.x << 5;                          // row offset in half2 units
}

// ---------------- propagation layer: y_out[d] = dinv2[d] * sum y_in[src]
// One warp per node; lane owns one half2 (4B) of the 128B fp16 row.
// g_csrc holds PRESCALED row offsets (src*32): per-gather address math is a
// single IADD (q.x + lane) instead of an IMAD.WIDE chain. Indices read
// 4-at-a-time via uniform int4 LDG, software-pipelined.
__global__ void layer_kernel(int layer, int N) {
    int warp = (blockIdx.x * blockDim.x + threadIdx.x) >> 5;
    int lane = threadIdx.x & 31;
    if (warp >= N) return;

    const half2* inp  = reinterpret_cast<const half2*>((layer == 0) ? g_y0 : g_y1);
    half2*       outp = reinterpret_cast<half2*>((layer == 0) ? g_y1 : g_y2);

    int beg = __ldg(&g_rowptr[warp]);
    int cnt = __ldg(&g_deg[warp]);
    int nq  = (cnt + 3) >> 2;
    const int4* qp = reinterpret_cast<const int4*>(g_csrc + beg);

    float2 acc = make_float2(0.f, 0.f);
    if (nq > 0) {
        int4 q = __ldg(qp);
        #pragma unroll 2
        for (int b = 1; b < nq; b++) {
            int4 qn = __ldg(qp + b);               // prefetch next indices
            float2 v0 = __half22float2(__ldg(&inp[(unsigned)(q.x + lane)]));
            float2 v1 = __half22float2(__ldg(&inp[(unsigned)(q.y + lane)]));
            float2 v2 = __half22float2(__ldg(&inp[(unsigned)(q.z + lane)]));
            float2 v3 = __half22float2(__ldg(&inp[(unsigned)(q.w + lane)]));
            acc.x += v0.x + v1.x + v2.x + v3.x;
            acc.y += v0.y + v1.y + v2.y + v3.y;
            q = qn;
        }
        float2 v0 = __half22float2(__ldg(&inp[(unsigned)(q.x + lane)]));
        float2 v1 = __half22float2(__ldg(&inp[(unsigned)(q.y + lane)]));
        float2 v2 = __half22float2(__ldg(&inp[(unsigned)(q.z + lane)]));
        float2 v3 = __half22float2(__ldg(&inp[(unsigned)(q.w + lane)]));
        acc.x += v0.x + v1.x + v2.x + v3.x;
        acc.y += v0.y + v1.y + v2.y + v3.y;
    }
    float w = __ldg(&g_dinv2[warp]);
    outp[(size_t)warp * 32 + lane] = __floats2half2_rn(w * acc.x, w * acc.y);
}

// ------- fused last layer + finalize:
// y3[d] = dinv2[d] * sum y2[src]   (never stored)
// out[0:nd)  = emb0
// out[nd:2nd)= (e0 + sqrt(deg[d])*(y1+y2+y3)) / 4
__global__ void layer3_finalize_kernel(const float* __restrict__ emb0,
                                       float* __restrict__ out, int N, long long nd2) {
    int warp = (blockIdx.x * blockDim.x + threadIdx.x) >> 5;
    int lane = threadIdx.x & 31;
    if (warp >= N) return;

    int beg = __ldg(&g_rowptr[warp]);
    int cnt = __ldg(&g_deg[warp]);
    int nq  = (cnt + 3) >> 2;
    const int4* qp = reinterpret_cast<const int4*>(g_csrc + beg);
    const half2* y2p = reinterpret_cast<const half2*>(g_y2);

    float2 acc = make_float2(0.f, 0.f);
    if (nq > 0) {
        int4 q = __ldg(qp);
        #pragma unroll 2
        for (int b = 1; b < nq; b++) {
            int4 qn = __ldg(qp + b);               // prefetch next indices
            float2 v0 = __half22float2(__ldg(&y2p[(unsigned)(q.x + lane)]));
            float2 v1 = __half22float2(__ldg(&y2p[(unsigned)(q.y + lane)]));
            float2 v2 = __half22float2(__ldg(&y2p[(unsigned)(q.z + lane)]));
            float2 v3 = __half22float2(__ldg(&y2p[(unsigned)(q.w + lane)]));
            acc.x += v0.x + v1.x + v2.x + v3.x;
            acc.y += v0.y + v1.y + v2.y + v3.y;
            q = qn;
        }
        float2 v0 = __half22float2(__ldg(&y2p[(unsigned)(q.x + lane)]));
        float2 v1 = __half22float2(__ldg(&y2p[(unsigned)(q.y + lane)]));
        float2 v2 = __half22float2(__ldg(&y2p[(unsigned)(q.z + lane)]));
        float2 v3 = __half22float2(__ldg(&y2p[(unsigned)(q.w + lane)]));
        acc.x += v0.x + v1.x + v2.x + v3.x;
        acc.y += v0.y + v1.y + v2.y + v3.y;
    }
    float w2 = __ldg(&g_dinv2[warp]);
    float rd = __ldg(&g_rdeg[warp]);
    long long idxo = (long long)warp * 32 + lane;

    float2 e0 = __ldg(reinterpret_cast<const float2*>(emb0) + idxo);
    float2 h1 = __half22float2(__ldg(reinterpret_cast<const half2*>(g_y1) + idxo));
    float2 h2 = __half22float2(__ldg(y2p + idxo));

    float2 r;
    r.x = 0.25f * (e0.x + rd * (h1.x + h2.x + w2 * acc.x));
    r.y = 0.25f * (e0.y + rd * (h1.y + h2.y + w2 * acc.y));

    float2* o = reinterpret_cast<float2*>(out);
    o[idxo] = e0;           // exact fp32 copy of emb0
    o[nd2 + idxo] = r;      // mean embedding
}

extern "C" void kernel_launch(void* const* d_in, const int* in_sizes, int n_in,
                              void* d_out, int out_size) {
    const int*   ei32 = (const int*)d_in[0];     // edge_index [2, E] (int32 or int64)
    const float* emb  = (const float*)d_in[1];   // emb_weight [N, D] float32
    int       E   = in_sizes[0] / 2;
    long long nd  = (long long)in_sizes[1];
    int       N   = (int)(nd / DIM);
    long long nd2 = nd / 2;                      // number of float2 chunks
    float* out = (float*)d_out;

    int nblk = (N + SCAN_BLK - 1) / SCAN_BLK;
    int eblk = (E + 255) / 256;
    int wblk = (N * 32 + 255) / 256;             // one warp per node
    int yblk = (N * 32 + 32 + 255) / 256;        // + sentinel row chunks

    // Fork/join plumbing (host objects only; capture-legal).
    cudaStream_t s2;
    cudaStreamCreateWithFlags(&s2, cudaStreamNonBlocking);
    cudaEvent_t evFork, evJoin;
    cudaEventCreateWithFlags(&evFork, cudaEventDisableTiming);
    cudaEventCreateWithFlags(&evJoin, cudaEventDisableTiming);

    zero_deg_kernel<<<(N + 255) / 256, 256>>>(N);
    build_edges_kernel<<<eblk, 256>>>(ei32, E, N);

    // Fork: dinv_y0 (DRAM-streaming) runs concurrent with scan+fill (L2-bound).
    cudaEventRecord(evFork, 0);
    cudaStreamWaitEvent(s2, evFork, 0);
    dinv_y0_kernel<<<yblk, 256, 0, s2>>>(emb, N);
    cudaEventRecord(evJoin, s2);

    scan1_kernel<<<nblk, SCAN_BLK>>>(N);
    scan2_kernel<<<1, MAX_NBLK>>>(nblk);
    scan3_kernel<<<nblk, SCAN_BLK>>>(N);
    fill_kernel<<<eblk, 256>>>(E);

    // Join before the layers consume y0/dinv tables.
    cudaStreamWaitEvent(0, evJoin, 0);

    layer_kernel<<<wblk, 256>>>(0, N);
    layer_kernel<<<wblk, 256>>>(1, N);
    layer3_finalize_kernel<<<wblk, 256>>>(emb, out, N, nd2);

    cudaEventDestroy(evFork);
    cudaEventDestroy(evJoin);
    cudaStreamDestroy(s2);
}